// round 5
// baseline (speedup 1.0000x reference)
#include <cuda_runtime.h>

// Problem constants
#define NTOK 16384      // B*H*W = 16*32*32
#define KC   8192       // codebook entries
#define DD   256        // feature dim (= C)
#define IMG  262144     // C*H*W
#define HW   1024       // H*W

#define OUT_LOSS 4194304
#define OUT_ENC  4194305

// GEMM tiling
#define BM 128
#define BN 256
#define BK 16
#define ASTR 132        // As row stride (floats)
#define BSTR2 516       // Bs row stride (floats), duplicated layout: 2*BN + 4

// dynamic smem partition (floats)
#define AS_ELEMS (2 * BK * ASTR)            // 4224
#define BS_ELEMS (2 * BK * BSTR2)           // 16512
#define SMEM_BYTES ((AS_ELEMS + BS_ELEMS) * 4)   // 82944

// -------- scratch (device globals; no allocation allowed) --------
__device__ float g_cnorm[KC];
__device__ float g_xnorm[NTOK];
__device__ int   g_idx[NTOK];
__device__ float g_partial[256];

// -------- f32x2 packed helpers --------
union F2U { float2 f; unsigned long long u; };

__device__ __forceinline__ unsigned long long pack2(float v) {
    unsigned long long r;
    asm("mov.b64 %0, {%1, %1};" : "=l"(r) : "r"(__float_as_uint(v)));
    return r;
}
__device__ __forceinline__ void fma2(unsigned long long& d,
                                     unsigned long long a,
                                     unsigned long long b) {
    asm("fma.rn.f32x2 %0, %1, %2, %0;" : "+l"(d) : "l"(a), "l"(b));
}
__device__ __forceinline__ unsigned long long fma2_3(unsigned long long a,
                                                     unsigned long long b,
                                                     unsigned long long c) {
    unsigned long long d;
    asm("fma.rn.f32x2 %0, %1, %2, %3;" : "=l"(d) : "l"(a), "l"(b), "l"(c));
    return d;
}
__device__ __forceinline__ unsigned long long add2(unsigned long long a,
                                                   unsigned long long b) {
    unsigned long long d;
    asm("add.rn.f32x2 %0, %1, %2;" : "=l"(d) : "l"(a), "l"(b));
    return d;
}

// ============================================================
// Kernel 1: norms (codebook + tokens), strict sequential chains
// s = fl(s + fl(v*v)), d ascending — bit-exact vs XLA-CPU sum.
// ============================================================
__global__ __launch_bounds__(256) void norms_kernel(const float* __restrict__ x,
                                                    const float* __restrict__ cb) {
    int blk = blockIdx.x;
    if (blk < 32) {
        int k = blk * 256 + threadIdx.x;
        const float* p = cb + (size_t)k * DD;
        float s = 0.f;
#pragma unroll 8
        for (int d = 0; d < DD; ++d) {
            float v = p[d];
            s = __fadd_rn(s, __fmul_rn(v, v));
        }
        g_cnorm[k] = s;
    } else {
        int n  = (blk - 32) * 256 + threadIdx.x;
        int b  = n >> 10;
        int hw = n & (HW - 1);
        const float* p = x + (size_t)b * IMG + hw;
        float s = 0.f;
#pragma unroll 8
        for (int d = 0; d < DD; ++d) {
            float v = p[(size_t)d * HW];
            s = __fadd_rn(s, __fmul_rn(v, v));
        }
        g_xnorm[n] = s;
    }
}

// ============================================================
// Kernel 2: fused distance GEMM + per-token argmin.
// 512 threads, tile 128x256, thread tile 8 tok x 8 codes.
// Bs holds each code value DUPLICATED ({v,v} adjacent): the packed
// FFMA2 B-operand is a single LDS.64 — no mov.b64 duplication insts.
// As read is a warp-broadcast (all lanes use warp's 8 tokens).
// Double-buffered, 16 barriers per K-chunk.
// dist = fl( fl(xnorm+cnorm) - 2*m ) via fma.f32x2(m,-2,S): bit-exact.
// ============================================================
__global__ __launch_bounds__(512, 1) void dist_kernel(const float* __restrict__ x,
                                                      const float* __restrict__ cb) {
    extern __shared__ float smem[];
    float* As = smem;                 // [2][BK][ASTR]
    float* Bs = smem + AS_ELEMS;      // [2][BK][BSTR2]

    const int tid = threadIdx.x;
    const int cx  = tid & 31;           // code lane 0..31
    const int tg  = tid >> 5;           // token group 0..15 (= warp id)
    const int tg8 = tg * 8;

    const int tok0 = blockIdx.x * BM;
    const int bimg = tok0 >> 10;
    const int hw0  = tok0 & (HW - 1);
    const float* xb = x + (size_t)bimg * IMG + hw0;

    // A loader: one float4; d-row = warp id, tokens consecutive (coalesced)
    const int ad  = tid >> 5;           // 0..15
    const int at4 = (tid & 31) * 4;     // 0..124
    // B loader: coalesced float2 per code row; 4 rows per thread
    const int bro = tid >> 3;           // 0..63 (+64*i)
    const int bd  = (tid & 7) * 2;      // d-pair 0,2,..,14

    const unsigned long long NEG2 = pack2(-2.0f);

    // token-pair xnorms, persistent in regs
    unsigned long long xp2[4];
#pragma unroll
    for (int i = 0; i < 4; ++i)
        xp2[i] = *(const unsigned long long*)&g_xnorm[tok0 + tg8 + 2 * i];

    float bestv[8];
    int   besti[8];
#pragma unroll
    for (int i = 0; i < 8; ++i) { bestv[i] = 3.4e38f; besti[i] = 0; }

#define BS_W(buf, d, c, v0, v1) do {                         \
        float2 _p; _p.x = (v0); _p.y = (v1);                 \
        *(float2*)&Bs[(buf) * (BK * BSTR2) + (d) * BSTR2 + 2 * (c)] = _p; \
    } while (0)

    for (int k0 = 0; k0 < KC; k0 += BN) {
        unsigned long long acc[4][8];
#pragma unroll
        for (int i = 0; i < 4; ++i)
#pragma unroll
            for (int j = 0; j < 8; ++j) acc[i][j] = 0ull;

        // ---- preload d-step 0 into buffer 0 ----
        {
            float4 av  = *(const float4*)(xb + (size_t)ad * HW + at4);
            float2 bv0 = *(const float2*)(cb + (size_t)(k0 + bro      ) * DD + bd);
            float2 bv1 = *(const float2*)(cb + (size_t)(k0 + bro +  64) * DD + bd);
            float2 bv2 = *(const float2*)(cb + (size_t)(k0 + bro + 128) * DD + bd);
            float2 bv3 = *(const float2*)(cb + (size_t)(k0 + bro + 192) * DD + bd);
            *(float4*)&As[ad * ASTR + at4] = av;
            BS_W(0, bd,     bro,       bv0.x, bv0.x);
            BS_W(0, bd + 1, bro,       bv0.y, bv0.y);
            BS_W(0, bd,     bro +  64, bv1.x, bv1.x);
            BS_W(0, bd + 1, bro +  64, bv1.y, bv1.y);
            BS_W(0, bd,     bro + 128, bv2.x, bv2.x);
            BS_W(0, bd + 1, bro + 128, bv2.y, bv2.y);
            BS_W(0, bd,     bro + 192, bv3.x, bv3.x);
            BS_W(0, bd + 1, bro + 192, bv3.y, bv3.y);
        }
        __syncthreads();

        for (int d0i = 0; d0i < BK; ++d0i) {   // 16 steps of 16 d's
            const int cur = d0i & 1;
            const int d0n = (d0i + 1) * BK;

            // prefetch next step into registers
            float4 av; float2 bv0, bv1, bv2, bv3;
            if (d0i < BK - 1) {
                av  = *(const float4*)(xb + (size_t)(d0n + ad) * HW + at4);
                bv0 = *(const float2*)(cb + (size_t)(k0 + bro      ) * DD + d0n + bd);
                bv1 = *(const float2*)(cb + (size_t)(k0 + bro +  64) * DD + d0n + bd);
                bv2 = *(const float2*)(cb + (size_t)(k0 + bro + 128) * DD + d0n + bd);
                bv3 = *(const float2*)(cb + (size_t)(k0 + bro + 192) * DD + d0n + bd);
            }

            const float* Ac = As + cur * (BK * ASTR) + tg8;
            const float* Bc = Bs + cur * (BK * BSTR2) + 2 * cx;

            // 16 dk from current buffer (ascending d: bit-exact chain)
#pragma unroll
            for (int dk = 0; dk < BK; ++dk) {
                const unsigned long long* a64 =
                    reinterpret_cast<const unsigned long long*>(Ac + dk * ASTR);
                const unsigned long long* b64 =
                    reinterpret_cast<const unsigned long long*>(Bc + dk * BSTR2);
                unsigned long long A0 = a64[0], A1 = a64[1], A2 = a64[2], A3 = a64[3];
#pragma unroll
                for (int j = 0; j < 8; ++j) {
                    unsigned long long B = b64[32 * j];   // {v,v} direct from smem
                    fma2(acc[0][j], A0, B);
                    fma2(acc[1][j], A1, B);
                    fma2(acc[2][j], A2, B);
                    fma2(acc[3][j], A3, B);
                }
            }

            if (d0i < BK - 1) {
                const int nxt = cur ^ 1;
                *(float4*)&As[nxt * (BK * ASTR) + ad * ASTR + at4] = av;
                BS_W(nxt, bd,     bro,       bv0.x, bv0.x);
                BS_W(nxt, bd + 1, bro,       bv0.y, bv0.y);
                BS_W(nxt, bd,     bro +  64, bv1.x, bv1.x);
                BS_W(nxt, bd + 1, bro +  64, bv1.y, bv1.y);
                BS_W(nxt, bd,     bro + 128, bv2.x, bv2.x);
                BS_W(nxt, bd + 1, bro + 128, bv2.y, bv2.y);
                BS_W(nxt, bd,     bro + 192, bv3.x, bv3.x);
                BS_W(nxt, bd + 1, bro + 192, bv3.y, bv3.y);
                __syncthreads();
            }
        }

        // ---- chunk epilogue: reference-rounded distances + running argmin ----
        // (regs only; next chunk's buf0 preload is hazard-free: last compute
        //  step read buf1, and buf0's readers all passed the d0i=14 barrier)
#pragma unroll
        for (int j = 0; j < 8; ++j) {
            int   k  = k0 + cx + 32 * j;
            unsigned long long cn2 = pack2(g_cnorm[k]);
#pragma unroll
            for (int i = 0; i < 4; ++i) {
                unsigned long long S2 = add2(xp2[i], cn2);   // fl(xn + cn)
                F2U D; D.u = fma2_3(acc[i][j], NEG2, S2);    // fl(S - 2m)
                if (D.f.x < bestv[2 * i])     { bestv[2 * i]     = D.f.x; besti[2 * i]     = k; }
                if (D.f.y < bestv[2 * i + 1]) { bestv[2 * i + 1] = D.f.y; besti[2 * i + 1] = k; }
            }
        }
        __syncthreads();   // buf0 preload of next chunk vs this chunk's readers
    }

    // warp-level argmin reduce across code-lanes (tie -> lowest index)
#pragma unroll
    for (int i = 0; i < 8; ++i) {
        float bv = bestv[i];
        int   bi = besti[i];
#pragma unroll
        for (int off = 16; off; off >>= 1) {
            float ov = __shfl_xor_sync(0xffffffffu, bv, off);
            int   ob = __shfl_xor_sync(0xffffffffu, bi, off);
            if (ov < bv || (ov == bv && ob < bi)) { bv = ov; bi = ob; }
        }
        if (cx == 0) g_idx[tok0 + tg8 + i] = bi;
    }
#undef BS_W
}

// ============================================================
// Kernel 3: gather quant, straight-through output, loss partial.
// out = fl(x + fl(q - x))
// ============================================================
__global__ __launch_bounds__(256) void epi_kernel(const float* __restrict__ x,
                                                  const float* __restrict__ cb,
                                                  float* __restrict__ out) {
    __shared__ int   sidx[64];
    __shared__ float swarp[8];

    const int tid  = threadIdx.x;
    const int tok0 = blockIdx.x * 64;
    const int bimg = tok0 >> 10;
    const int hw0  = tok0 & (HW - 1);

    if (tid < 64) sidx[tid] = g_idx[tok0 + tid];
    __syncthreads();

    const int m  = tid & 63;
    const int dh = tid >> 6;                 // 0..3
    const size_t base = (size_t)bimg * IMG + hw0 + m;
    const long long crow = (long long)sidx[m] * DD;

    float lsum = 0.f;
#pragma unroll 8
    for (int d0 = 0; d0 < DD; d0 += 4) {
        int d = d0 + dh;
        float q  = cb[crow + d];
        size_t off = base + (size_t)d * HW;
        float xv = x[off];
        float t  = __fsub_rn(q, xv);        // fl(q - x)
        out[off] = __fadd_rn(xv, t);        // fl(x + fl(q - x))
        lsum = fmaf(t, t, lsum);
    }

#pragma unroll
    for (int off = 16; off; off >>= 1) lsum += __shfl_xor_sync(0xffffffffu, lsum, off);
    if ((tid & 31) == 0) swarp[tid >> 5] = lsum;
    __syncthreads();
    if (tid == 0) {
        float s = 0.f;
        for (int w = 0; w < 8; ++w) s += swarp[w];
        g_partial[blockIdx.x] = s;          // fixed-order -> deterministic
    }
    if (tid < 64) out[OUT_ENC + tok0 + tid] = (float)sidx[tid];
}

// ============================================================
// Kernel 4: finalize loss (deterministic tree over 256 partials)
// ============================================================
__global__ __launch_bounds__(256) void fin_kernel(float* __restrict__ out) {
    __shared__ float sw[8];
    int tid = threadIdx.x;
    float s = g_partial[tid];
#pragma unroll
    for (int off = 16; off; off >>= 1) s += __shfl_xor_sync(0xffffffffu, s, off);
    if ((tid & 31) == 0) sw[tid >> 5] = s;
    __syncthreads();
    if (tid == 0) {
        float tot = 0.f;
        for (int w = 0; w < 8; ++w) tot += sw[w];
        float mse = tot / 4194304.0f;
        out[OUT_LOSS] = __fadd_rn(mse, __fmul_rn(0.25f, mse));
    }
}

// ============================================================
extern "C" void kernel_launch(void* const* d_in, const int* in_sizes, int n_in,
                              void* d_out, int out_size) {
    const float* x  = (const float*)d_in[0];   // [16,256,32,32] fp32
    const float* cb = (const float*)d_in[1];   // [8192,256] fp32
    float* out = (float*)d_out;                // [quant | loss | encodings] fp32

    cudaFuncSetAttribute(dist_kernel,
                         cudaFuncAttributeMaxDynamicSharedMemorySize, SMEM_BYTES);

    norms_kernel<<<96, 256>>>(x, cb);
    dist_kernel<<<NTOK / BM, 512, SMEM_BYTES>>>(x, cb);
    epi_kernel<<<256, 256>>>(x, cb, out);
    fin_kernel<<<1, 256>>>(out);
}

// round 6
// speedup vs baseline: 1.0975x; 1.0975x over previous
#include <cuda_runtime.h>

// Problem constants
#define NTOK 16384      // B*H*W = 16*32*32
#define KC   8192       // codebook entries
#define DD   256        // feature dim (= C)
#define IMG  262144     // C*H*W
#define HW   1024       // H*W

#define OUT_LOSS 4194304
#define OUT_ENC  4194305

// GEMM tiling
#define BM 128
#define BN 256
#define BK 16
#define ASTRD 260       // As_dup row stride (floats): 256 dup-floats + pad, mult of 4
#define BSTR  258       // Bs row stride (floats): conflict-free transpose STS

// dynamic smem partition (floats)
#define AS_ELEMS (2 * BK * ASTRD)           // 8320
#define BS_ELEMS (2 * BK * BSTR)            // 8256
#define SMEM_BYTES ((AS_ELEMS + BS_ELEMS) * 4)   // 66304

typedef unsigned long long u64;

// -------- scratch (device globals; no allocation allowed) --------
__device__ float g_cnorm[KC];
__device__ float g_xnorm[NTOK];
__device__ int   g_idx[NTOK];
__device__ float g_partial[256];

// -------- f32x2 packed helpers --------
union F2U { float2 f; u64 u; };

__device__ __forceinline__ u64 pack2(float v) {
    u64 r;
    asm("mov.b64 %0, {%1, %1};" : "=l"(r) : "r"(__float_as_uint(v)));
    return r;
}
__device__ __forceinline__ void fma2(u64& d, u64 a, u64 b) {
    asm("fma.rn.f32x2 %0, %1, %2, %0;" : "+l"(d) : "l"(a), "l"(b));
}
__device__ __forceinline__ u64 fma2_3(u64 a, u64 b, u64 c) {
    u64 d;
    asm("fma.rn.f32x2 %0, %1, %2, %3;" : "=l"(d) : "l"(a), "l"(b), "l"(c));
    return d;
}
__device__ __forceinline__ u64 add2(u64 a, u64 b) {
    u64 d;
    asm("add.rn.f32x2 %0, %1, %2;" : "=l"(d) : "l"(a), "l"(b));
    return d;
}

// ============================================================
// Kernel 1: norms (codebook + tokens), strict sequential chains
// s = fl(s + fl(v*v)), d ascending — bit-exact vs XLA-CPU sum.
// ============================================================
__global__ __launch_bounds__(256) void norms_kernel(const float* __restrict__ x,
                                                    const float* __restrict__ cb) {
    int blk = blockIdx.x;
    if (blk < 32) {
        int k = blk * 256 + threadIdx.x;
        const float* p = cb + (size_t)k * DD;
        float s = 0.f;
#pragma unroll 8
        for (int d = 0; d < DD; ++d) {
            float v = p[d];
            s = __fadd_rn(s, __fmul_rn(v, v));
        }
        g_cnorm[k] = s;
    } else {
        int n  = (blk - 32) * 256 + threadIdx.x;
        int b  = n >> 10;
        int hw = n & (HW - 1);
        const float* p = x + (size_t)b * IMG + hw;
        float s = 0.f;
#pragma unroll 8
        for (int d = 0; d < DD; ++d) {
            float v = p[(size_t)d * HW];
            s = __fadd_rn(s, __fmul_rn(v, v));
        }
        g_xnorm[n] = s;
    }
}

// ============================================================
// Kernel 2: fused distance GEMM + per-token argmin.
// 512 threads, tile 128x256, thread tile 8 tokens x 8 codes.
// f32x2 packs CODE PAIRS: acc{c0,c1} += {A,A} * {B[c0],B[c1]}.
//   B operand: one LDS.64 of adjacent codes (normal [d][code] layout).
//   A operand: broadcast LDS.128 from token-duplicated As_dup {v,v}
//              (duplication is free on the broadcast operand).
// Per warp per dk: 4 LDS.128(A,bcast) + 4 LDS.64(B) + 32 FFMA2.
// Double-buffered, 16 barriers per K-chunk.
// dist = fl( fl(xnorm+cnorm) - 2*m ) via fma.f32x2(m,-2,S): bit-exact.
// ============================================================
__global__ __launch_bounds__(512, 1) void dist_kernel(const float* __restrict__ x,
                                                      const float* __restrict__ cb) {
    extern __shared__ float smem[];
    float* As = smem;                 // [2][BK][ASTRD] token-duplicated
    float* Bs = smem + AS_ELEMS;      // [2][BK][BSTR]

    const int tid = threadIdx.x;
    const int cx  = tid & 31;           // lane: code-pair base 2*cx
    const int tg  = tid >> 5;           // token group 0..15 (= warp id)
    const int tg8 = tg * 8;

    const int tok0 = blockIdx.x * BM;
    const int bimg = tok0 >> 10;
    const int hw0  = tok0 & (HW - 1);
    const float* xb = x + (size_t)bimg * IMG + hw0;

    // A loader: d-row = warp id; tokens lane+32i (i<4), coalesced LDG.32,
    //           stored duplicated {v,v} -> STS.64, banks 2*ad+lane: conflict-free
    const int ad    = tid >> 5;         // 0..15
    const int alane = tid & 31;
    // B loader: coalesced float2 per code row; 4 rows per thread (round-4 proven)
    const int bro = tid >> 3;           // 0..63 (+64*i)
    const int bd  = (tid & 7) * 2;      // d-pair 0,2,..,14

    const u64 NEG2 = pack2(-2.0f);

    // token norms (scalar; packed on demand in epilogue)
    float xr[8];
#pragma unroll
    for (int i = 0; i < 8; ++i) xr[i] = g_xnorm[tok0 + tg8 + i];

    float bestv[8];
    int   besti[8];
#pragma unroll
    for (int i = 0; i < 8; ++i) { bestv[i] = 3.4e38f; besti[i] = 0; }

#define A_STORE(buf, d, av)  do {                                          \
        float2 _w; _w.x = (av); _w.y = (av);                               \
        *(float2*)&As[(buf) * (BK * ASTRD) + (d) * ASTRD + 2 * (alane) + 64 * _i] = _w; \
    } while (0)

    for (int k0 = 0; k0 < KC; k0 += BN) {
        u64 acc[8][4];
#pragma unroll
        for (int t = 0; t < 8; ++t)
#pragma unroll
            for (int j = 0; j < 4; ++j) acc[t][j] = 0ull;

        // ---- preload d-step 0 into buffer 0 ----
        {
#pragma unroll
            for (int _i = 0; _i < 4; ++_i) {
                float av = xb[(size_t)ad * HW + alane + 32 * _i];
                A_STORE(0, ad, av);
            }
            float2 bv0 = *(const float2*)(cb + (size_t)(k0 + bro      ) * DD + bd);
            float2 bv1 = *(const float2*)(cb + (size_t)(k0 + bro +  64) * DD + bd);
            float2 bv2 = *(const float2*)(cb + (size_t)(k0 + bro + 128) * DD + bd);
            float2 bv3 = *(const float2*)(cb + (size_t)(k0 + bro + 192) * DD + bd);
            Bs[bd * BSTR + bro]             = bv0.x; Bs[(bd + 1) * BSTR + bro]       = bv0.y;
            Bs[bd * BSTR + bro + 64]        = bv1.x; Bs[(bd + 1) * BSTR + bro + 64]  = bv1.y;
            Bs[bd * BSTR + bro + 128]       = bv2.x; Bs[(bd + 1) * BSTR + bro + 128] = bv2.y;
            Bs[bd * BSTR + bro + 192]       = bv3.x; Bs[(bd + 1) * BSTR + bro + 192] = bv3.y;
        }
        __syncthreads();

        for (int d0i = 0; d0i < BK; ++d0i) {   // 16 steps of 16 d's
            const int cur = d0i & 1;
            const int d0n = (d0i + 1) * BK;

            // prefetch next step into registers
            float av[4]; float2 bv0, bv1, bv2, bv3;
            if (d0i < BK - 1) {
#pragma unroll
                for (int i = 0; i < 4; ++i)
                    av[i] = xb[(size_t)(d0n + ad) * HW + alane + 32 * i];
                bv0 = *(const float2*)(cb + (size_t)(k0 + bro      ) * DD + d0n + bd);
                bv1 = *(const float2*)(cb + (size_t)(k0 + bro +  64) * DD + d0n + bd);
                bv2 = *(const float2*)(cb + (size_t)(k0 + bro + 128) * DD + d0n + bd);
                bv3 = *(const float2*)(cb + (size_t)(k0 + bro + 192) * DD + d0n + bd);
            }

            const float* Ac = As + cur * (BK * ASTRD) + 2 * tg8;  // 64B-aligned
            const float* Bc = Bs + cur * (BK * BSTR) + 2 * cx;

            // 16 dk from current buffer (ascending d: bit-exact chain)
#pragma unroll
            for (int dk = 0; dk < BK; ++dk) {
                const longlong2* a2 =
                    reinterpret_cast<const longlong2*>(Ac + dk * ASTRD);
                longlong2 p0 = a2[0], p1 = a2[1], p2 = a2[2], p3 = a2[3]; // broadcast
                const u64* b64 = reinterpret_cast<const u64*>(Bc + dk * BSTR);
                u64 B0 = b64[0], B1 = b64[32], B2 = b64[64], B3 = b64[96];

                fma2(acc[0][0], (u64)p0.x, B0); fma2(acc[0][1], (u64)p0.x, B1);
                fma2(acc[0][2], (u64)p0.x, B2); fma2(acc[0][3], (u64)p0.x, B3);
                fma2(acc[1][0], (u64)p0.y, B0); fma2(acc[1][1], (u64)p0.y, B1);
                fma2(acc[1][2], (u64)p0.y, B2); fma2(acc[1][3], (u64)p0.y, B3);
                fma2(acc[2][0], (u64)p1.x, B0); fma2(acc[2][1], (u64)p1.x, B1);
                fma2(acc[2][2], (u64)p1.x, B2); fma2(acc[2][3], (u64)p1.x, B3);
                fma2(acc[3][0], (u64)p1.y, B0); fma2(acc[3][1], (u64)p1.y, B1);
                fma2(acc[3][2], (u64)p1.y, B2); fma2(acc[3][3], (u64)p1.y, B3);
                fma2(acc[4][0], (u64)p2.x, B0); fma2(acc[4][1], (u64)p2.x, B1);
                fma2(acc[4][2], (u64)p2.x, B2); fma2(acc[4][3], (u64)p2.x, B3);
                fma2(acc[5][0], (u64)p2.y, B0); fma2(acc[5][1], (u64)p2.y, B1);
                fma2(acc[5][2], (u64)p2.y, B2); fma2(acc[5][3], (u64)p2.y, B3);
                fma2(acc[6][0], (u64)p3.x, B0); fma2(acc[6][1], (u64)p3.x, B1);
                fma2(acc[6][2], (u64)p3.x, B2); fma2(acc[6][3], (u64)p3.x, B3);
                fma2(acc[7][0], (u64)p3.y, B0); fma2(acc[7][1], (u64)p3.y, B1);
                fma2(acc[7][2], (u64)p3.y, B2); fma2(acc[7][3], (u64)p3.y, B3);
            }

            if (d0i < BK - 1) {
                const int nxt = cur ^ 1;
#pragma unroll
                for (int _i = 0; _i < 4; ++_i) A_STORE(nxt, ad, av[_i]);
                float* Bn = Bs + nxt * (BK * BSTR);
                Bn[bd * BSTR + bro]       = bv0.x; Bn[(bd + 1) * BSTR + bro]       = bv0.y;
                Bn[bd * BSTR + bro + 64]  = bv1.x; Bn[(bd + 1) * BSTR + bro + 64]  = bv1.y;
                Bn[bd * BSTR + bro + 128] = bv2.x; Bn[(bd + 1) * BSTR + bro + 128] = bv2.y;
                Bn[bd * BSTR + bro + 192] = bv3.x; Bn[(bd + 1) * BSTR + bro + 192] = bv3.y;
                __syncthreads();
            }
        }

        // ---- chunk epilogue: reference-rounded distances + running argmin ----
        // k = k0 + 2*cx + 64*j + {0,1}; j ascending, lo before hi -> k ascending
#pragma unroll
        for (int j = 0; j < 4; ++j) {
            const int kb = k0 + 2 * cx + 64 * j;
            u64 cn2 = *(const u64*)&g_cnorm[kb];      // coalesced pair load
#pragma unroll
            for (int t = 0; t < 8; ++t) {
                u64 S2 = add2(pack2(xr[t]), cn2);     // fl(xn + cn) each half
                F2U D; D.u = fma2_3(acc[t][j], NEG2, S2);  // fl(S - 2m)
                if (D.f.x < bestv[t]) { bestv[t] = D.f.x; besti[t] = kb; }
                if (D.f.y < bestv[t]) { bestv[t] = D.f.y; besti[t] = kb + 1; }
            }
        }
        // no trailing barrier needed: next chunk's preload writes buf0 whose
        // last readers passed the post-step-14 barrier; step-15 reads buf1 only.
    }

    // warp-level argmin reduce across lanes (tie -> lowest index)
#pragma unroll
    for (int i = 0; i < 8; ++i) {
        float bv = bestv[i];
        int   bi = besti[i];
#pragma unroll
        for (int off = 16; off; off >>= 1) {
            float ov = __shfl_xor_sync(0xffffffffu, bv, off);
            int   ob = __shfl_xor_sync(0xffffffffu, bi, off);
            if (ov < bv || (ov == bv && ob < bi)) { bv = ov; bi = ob; }
        }
        if (cx == 0) g_idx[tok0 + tg8 + i] = bi;
    }
#undef A_STORE
}

// ============================================================
// Kernel 3: gather quant, straight-through output, loss partial.
// out = fl(x + fl(q - x))
// ============================================================
__global__ __launch_bounds__(256) void epi_kernel(const float* __restrict__ x,
                                                  const float* __restrict__ cb,
                                                  float* __restrict__ out) {
    __shared__ int   sidx[64];
    __shared__ float swarp[8];

    const int tid  = threadIdx.x;
    const int tok0 = blockIdx.x * 64;
    const int bimg = tok0 >> 10;
    const int hw0  = tok0 & (HW - 1);

    if (tid < 64) sidx[tid] = g_idx[tok0 + tid];
    __syncthreads();

    const int m  = tid & 63;
    const int dh = tid >> 6;                 // 0..3
    const size_t base = (size_t)bimg * IMG + hw0 + m;
    const long long crow = (long long)sidx[m] * DD;

    float lsum = 0.f;
#pragma unroll 8
    for (int d0 = 0; d0 < DD; d0 += 4) {
        int d = d0 + dh;
        float q  = cb[crow + d];
        size_t off = base + (size_t)d * HW;
        float xv = x[off];
        float t  = __fsub_rn(q, xv);        // fl(q - x)
        out[off] = __fadd_rn(xv, t);        // fl(x + fl(q - x))
        lsum = fmaf(t, t, lsum);
    }

#pragma unroll
    for (int off = 16; off; off >>= 1) lsum += __shfl_xor_sync(0xffffffffu, lsum, off);
    if ((tid & 31) == 0) swarp[tid >> 5] = lsum;
    __syncthreads();
    if (tid == 0) {
        float s = 0.f;
        for (int w = 0; w < 8; ++w) s += swarp[w];
        g_partial[blockIdx.x] = s;          // fixed-order -> deterministic
    }
    if (tid < 64) out[OUT_ENC + tok0 + tid] = (float)sidx[tid];
}

// ============================================================
// Kernel 4: finalize loss (deterministic tree over 256 partials)
// ============================================================
__global__ __launch_bounds__(256) void fin_kernel(float* __restrict__ out) {
    __shared__ float sw[8];
    int tid = threadIdx.x;
    float s = g_partial[tid];
#pragma unroll
    for (int off = 16; off; off >>= 1) s += __shfl_xor_sync(0xffffffffu, s, off);
    if ((tid & 31) == 0) sw[tid >> 5] = s;
    __syncthreads();
    if (tid == 0) {
        float tot = 0.f;
        for (int w = 0; w < 8; ++w) tot += sw[w];
        float mse = tot / 4194304.0f;
        out[OUT_LOSS] = __fadd_rn(mse, __fmul_rn(0.25f, mse));
    }
}

// ============================================================
extern "C" void kernel_launch(void* const* d_in, const int* in_sizes, int n_in,
                              void* d_out, int out_size) {
    const float* x  = (const float*)d_in[0];   // [16,256,32,32] fp32
    const float* cb = (const float*)d_in[1];   // [8192,256] fp32
    float* out = (float*)d_out;                // [quant | loss | encodings] fp32

    cudaFuncSetAttribute(dist_kernel,
                         cudaFuncAttributeMaxDynamicSharedMemorySize, SMEM_BYTES);

    norms_kernel<<<96, 256>>>(x, cb);
    dist_kernel<<<NTOK / BM, 512, SMEM_BYTES>>>(x, cb);
    epi_kernel<<<256, 256>>>(x, cb, out);
    fin_kernel<<<1, 256>>>(out);
}

// round 8
// speedup vs baseline: 2.0383x; 1.8573x over previous
#include <cuda_runtime.h>
#include <cuda_bf16.h>

// Problem constants
#define NTOK 16384      // B*H*W
#define KC   8192
#define DD   256
#define IMG  262144     // C*H*W
#define HW   1024

#define OUT_LOSS 4194304
#define OUT_ENC  4194305

// GEMM tiling: M = codes, N = tokens
#define CTM 128         // codes per CTA
#define CTN 256         // tokens per CTA
#define CK  32          // d per chunk
#define NCH (DD / CK)   // 8

#define EPS_WIN  1.0e-3f
#define CAND_CAP 64

typedef unsigned int u32;

// -------- scratch (device globals; no allocation allowed) --------
__device__ float g_cnorm[KC];
__device__ float g_xnorm[NTOK];
__device__ int   g_idx[NTOK];
__device__ float g_partial[256];
__device__ u32   g_dmin[NTOK];
__device__ int   g_ccnt[NTOK];
__device__ int   g_cand[NTOK * CAND_CAP];
__device__ __align__(16) __nv_bfloat16 g_xb[NTOK * DD];     // x layout [b][d][hw], bf16
__device__ __align__(16) __nv_bfloat16 g_cbb[KC * DD];      // [code][d] bf16
__device__ __align__(16) __nv_bfloat16 g_dtil[134217728];   // [code][token] 256MB

// -------- helpers --------
__device__ __forceinline__ u32 smem_u32(const void* p) {
    u32 a;
    asm("{ .reg .u64 t; cvta.to.shared.u64 t, %1; cvt.u32.u64 %0, t; }" : "=r"(a) : "l"(p));
    return a;
}
__device__ __forceinline__ void ldsm4(u32& r0, u32& r1, u32& r2, u32& r3, u32 a) {
    asm volatile("ldmatrix.sync.aligned.m8n8.x4.shared.b16 {%0,%1,%2,%3}, [%4];"
                 : "=r"(r0), "=r"(r1), "=r"(r2), "=r"(r3) : "r"(a));
}
__device__ __forceinline__ void ldsm4t(u32& r0, u32& r1, u32& r2, u32& r3, u32 a) {
    asm volatile("ldmatrix.sync.aligned.m8n8.x4.trans.shared.b16 {%0,%1,%2,%3}, [%4];"
                 : "=r"(r0), "=r"(r1), "=r"(r2), "=r"(r3) : "r"(a));
}
__device__ __forceinline__ void mma16816(float* c, const u32* a, u32 b0, u32 b1) {
    asm volatile("mma.sync.aligned.m16n8k16.row.col.f32.bf16.bf16.f32 "
                 "{%0,%1,%2,%3}, {%4,%5,%6,%7}, {%8,%9}, {%0,%1,%2,%3};"
                 : "+f"(c[0]), "+f"(c[1]), "+f"(c[2]), "+f"(c[3])
                 : "r"(a[0]), "r"(a[1]), "r"(a[2]), "r"(a[3]), "r"(b0), "r"(b1));
}
__device__ __forceinline__ u32 pack_bf(float lo, float hi) {  // lo -> bits[0:16)
    u32 r;
    asm("cvt.rn.bf16x2.f32 %0, %1, %2;" : "=r"(r) : "f"(hi), "f"(lo));
    return r;
}
__device__ __forceinline__ u32 fkey(float f) {   // orderable-uint encode
    u32 b = __float_as_uint(f);
    return (b & 0x80000000u) ? ~b : (b | 0x80000000u);
}

// ============================================================
// Kernel 1: exact norms (strict sequential fp32 chains) + inits
// ============================================================
__global__ __launch_bounds__(256) void norms_kernel(const float* __restrict__ x,
                                                    const float* __restrict__ cb) {
    int blk = blockIdx.x;
    if (blk < 32) {
        int k = blk * 256 + threadIdx.x;
        const float* p = cb + (size_t)k * DD;
        float s = 0.f;
#pragma unroll 8
        for (int d = 0; d < DD; ++d) { float v = p[d]; s = __fadd_rn(s, __fmul_rn(v, v)); }
        g_cnorm[k] = s;
    } else {
        int n  = (blk - 32) * 256 + threadIdx.x;
        int b  = n >> 10, hw = n & (HW - 1);
        const float* p = x + (size_t)b * IMG + hw;
        float s = 0.f;
#pragma unroll 8
        for (int d = 0; d < DD; ++d) { float v = p[(size_t)d * HW]; s = __fadd_rn(s, __fmul_rn(v, v)); }
        g_xnorm[n] = s;
        g_dmin[n]  = 0xFFFFFFFFu;
        g_ccnt[n]  = 0;
    }
}

// ============================================================
// Kernel 2: convert x and cb to bf16 once (halves GEMM L2 traffic)
// ============================================================
__global__ __launch_bounds__(256) void convert_kernel(const float* __restrict__ x,
                                                      const float* __restrict__ cb) {
    size_t i = ((size_t)blockIdx.x * 256 + threadIdx.x) * 8;
    const float4* s;
    __nv_bfloat16* d;
    if (i < (size_t)NTOK * DD) { s = (const float4*)(x + i);                d = g_xb + i; }
    else { size_t j = i - (size_t)NTOK * DD; s = (const float4*)(cb + j);   d = g_cbb + j; }
    float4 v0 = s[0], v1 = s[1];
    uint4 w;
    w.x = pack_bf(v0.x, v0.y); w.y = pack_bf(v0.z, v0.w);
    w.z = pack_bf(v1.x, v1.y); w.w = pack_bf(v1.z, v1.w);
    *(uint4*)d = w;
}

// ============================================================
// Kernel 3: HMMA bf16 prescreen GEMM (mma.sync.m16n8k16).
// CTA 128 codes x 256 tokens, 512 threads (16 warps = 4 wm x 4 wn).
// A = g_cbb [code][d] (ldmatrix), B = g_xb [d][token] (ldmatrix.trans).
// Epilogue: dtil[code][token] = bf16(cn - 2*m), per-token min atomics.
// ============================================================
__global__ __launch_bounds__(512, 1) void gemm_kernel() {
    __shared__ __align__(16) char sm[49152];   // A 2x8KB @0, B 2x16KB @16384
    const u32 smU = smem_u32(sm);
    const int tid  = threadIdx.x;
    const int lane = tid & 31;
    const int wid  = tid >> 5;
    const int wm   = wid & 3;      // code group (32 codes)
    const int wn   = wid >> 2;     // token group (64 tokens)

    const int code0 = (blockIdx.x & 63) * CTM;
    const int tok0  = (blockIdx.x >> 6) * CTN;
    const int bimg  = tok0 >> 10;
    const int hw0   = tok0 & (HW - 1);

    // A loader: row = tid>>2 (0..127), chunk = tid&3 ; coalesced uint4
    const int arow = tid >> 2, ac = tid & 3;
    const __nv_bfloat16* aG = g_cbb + (size_t)(code0 + arow) * DD + ac * 8;
    const u32 aOff = (u32)arow * 64u + (u32)((ac ^ ((arow >> 1) & 3))) * 16u;
    // B loader: d = tid>>4 (0..31), chunks tid&15 and +16 ; coalesced uint4 x2
    const int bd = tid >> 4, bc = tid & 15;
    const __nv_bfloat16* bG = g_xb + (size_t)bimg * IMG + hw0 + (size_t)bd * HW + bc * 8;
    const u32 bOff0 = 16384u + (u32)bd * 512u + (u32)((bc        ^ (bd & 7))) * 16u;
    const u32 bOff1 = 16384u + (u32)bd * 512u + (u32)(((bc + 16) ^ (bd & 7))) * 16u;

    float acc[2][8][4];
#pragma unroll
    for (int mi = 0; mi < 2; ++mi)
#pragma unroll
        for (int nt = 0; nt < 8; ++nt)
#pragma unroll
            for (int q = 0; q < 4; ++q) acc[mi][nt][q] = 0.f;

    // prologue: chunk 0 -> buffer 0
    uint4 aR  = *(const uint4*)aG;
    uint4 bR0 = *(const uint4*)bG;
    uint4 bR1 = *(const uint4*)(bG + 128);
    *(uint4*)(sm + aOff)  = aR;
    *(uint4*)(sm + bOff0) = bR0;
    *(uint4*)(sm + bOff1) = bR1;
    __syncthreads();

    const int sa = ((lane & 15) >> 1) & 3;
    const int sb = lane & 7;
    const u32 aFragBase = smU + (u32)(wm * 32 + (lane & 15)) * 64u;
    const u32 bFragBase = smU + 16384u + (u32)(lane & 15) * 512u;

    for (int ch = 0; ch < NCH; ++ch) {
        const int p = ch & 1;
        if (ch < NCH - 1) {
            aR  = *(const uint4*)(aG + (ch + 1) * CK);
            bR0 = *(const uint4*)(bG + (size_t)(ch + 1) * CK * HW);
            bR1 = *(const uint4*)(bG + (size_t)(ch + 1) * CK * HW + 128);
        }
#pragma unroll
        for (int kk = 0; kk < 2; ++kk) {
            u32 a0[4], a1[4];
            const u32 aTop = (u32)(((kk * 2 + (lane >> 4)) ^ sa)) * 16u + (u32)p * 8192u;
            ldsm4(a0[0], a0[1], a0[2], a0[3], aFragBase + aTop);
            ldsm4(a1[0], a1[1], a1[2], a1[3], aFragBase + 1024u + aTop);
            const u32 bRow = (u32)p * 16384u + (u32)(kk * 16) * 512u;
#pragma unroll
            for (int np = 0; np < 4; ++np) {
                u32 b0, b1, b2, b3;
                const u32 c = (u32)(((wn * 8 + np * 2 + (lane >> 4)) ^ sb)) * 16u;
                ldsm4t(b0, b1, b2, b3, bFragBase + bRow + c);
                mma16816(acc[0][2 * np],     a0, b0, b1);
                mma16816(acc[0][2 * np + 1], a0, b2, b3);
                mma16816(acc[1][2 * np],     a1, b0, b1);
                mma16816(acc[1][2 * np + 1], a1, b2, b3);
            }
        }
        if (ch < NCH - 1) {
            const u32 q = (u32)(p ^ 1);
            __syncthreads();                       // all reads of buf q done
            *(uint4*)(sm + q * 8192u  + aOff)  = aR;
            *(uint4*)(sm + q * 16384u + bOff0) = bR0;
            *(uint4*)(sm + q * 16384u + bOff1) = bR1;
            __syncthreads();                       // buf q ready
        }
    }

    // ---- epilogue: dtil store + per-token min ----
    float tmn[8][2];
#pragma unroll
    for (int nt = 0; nt < 8; ++nt) { tmn[nt][0] = 3.4e38f; tmn[nt][1] = 3.4e38f; }
#pragma unroll
    for (int mi = 0; mi < 2; ++mi)
#pragma unroll
        for (int h = 0; h < 2; ++h) {
            const int code = code0 + wm * 32 + mi * 16 + (lane >> 2) + h * 8;
            const float cn = g_cnorm[code];
            __nv_bfloat16* dst = g_dtil + (size_t)code * NTOK + tok0 + wn * 64 + 2 * (lane & 3);
#pragma unroll
            for (int nt = 0; nt < 8; ++nt) {
                float dv0 = fmaf(-2.f, acc[mi][nt][h * 2 + 0], cn);
                float dv1 = fmaf(-2.f, acc[mi][nt][h * 2 + 1], cn);
                u32 w = pack_bf(dv0, dv1);
                *(u32*)(dst + (size_t)nt * 8) = w;
                float f0 = __bfloat162float(__ushort_as_bfloat16((unsigned short)(w & 0xFFFFu)));
                float f1 = __bfloat162float(__ushort_as_bfloat16((unsigned short)(w >> 16)));
                tmn[nt][0] = fminf(tmn[nt][0], f0);
                tmn[nt][1] = fminf(tmn[nt][1], f1);
            }
        }
#pragma unroll
    for (int nt = 0; nt < 8; ++nt)
#pragma unroll
        for (int off = 16; off >= 4; off >>= 1) {
            tmn[nt][0] = fminf(tmn[nt][0], __shfl_xor_sync(0xffffffffu, tmn[nt][0], off));
            tmn[nt][1] = fminf(tmn[nt][1], __shfl_xor_sync(0xffffffffu, tmn[nt][1], off));
        }
    if (lane < 4) {
#pragma unroll
        for (int nt = 0; nt < 8; ++nt) {
            int t = tok0 + wn * 64 + nt * 8 + 2 * lane;
            atomicMin(&g_dmin[t],     fkey(tmn[nt][0]));
            atomicMin(&g_dmin[t + 1], fkey(tmn[nt][1]));
        }
    }
}

// ============================================================
// Kernel 4: candidate collection — coalesced scan of dtil columns.
// grid 512 = 64 token-blocks x 8 code-slices of 1024.
// ============================================================
__global__ __launch_bounds__(256) void collect_kernel() {
    const int token = (blockIdx.x & 63) * 256 + threadIdx.x;
    const int k0    = (blockIdx.x >> 6) * 1024;
    const u32 key = g_dmin[token];
    const u32 mb  = (key & 0x80000000u) ? (key ^ 0x80000000u) : ~key;
    const float thr = __uint_as_float(mb) + EPS_WIN;
    const __nv_bfloat16* col = g_dtil + token;
#pragma unroll 16
    for (int k = k0; k < k0 + 1024; ++k) {
        float f = __bfloat162float(col[(size_t)k * NTOK]);
        if (f <= thr) {
            int p = atomicAdd(&g_ccnt[token], 1);
            if (p < CAND_CAP) g_cand[token * CAND_CAP + p] = k;
        }
    }
}

// ============================================================
// Kernel 5: EXACT rescore of candidates (bit-exact ascending-d chain,
// reference-rounded d, lex-min (d,k) = jnp.argmin semantics).
// Warp per token; full-scan fallback on candidate overflow.
// ============================================================
__global__ __launch_bounds__(256) void rescore_kernel(const float* __restrict__ x,
                                                      const float* __restrict__ cb) {
    __shared__ float xs[8][DD];
    const int tid = threadIdx.x, w = tid >> 5, lane = tid & 31;
    const int n = blockIdx.x * 8 + w;
    const int b = n >> 10, hw = n & (HW - 1);
    const float* xp = x + (size_t)b * IMG + hw;
#pragma unroll
    for (int d = lane; d < DD; d += 32) xs[w][d] = xp[(size_t)d * HW];
    __syncwarp();

    const int cnt = g_ccnt[n];
    const float xn = g_xnorm[n];
    float bv = 3.4e38f;
    int   bi = 0x7FFFFFFF;

    if (cnt <= CAND_CAP) {
        for (int ci = lane; ci < cnt; ci += 32) {
            int k = g_cand[n * CAND_CAP + ci];
            const float* cp = cb + (size_t)k * DD;
            float m = 0.f;
#pragma unroll 8
            for (int d = 0; d < DD; ++d) m = fmaf(xs[w][d], cp[d], m);
            float dd = __fsub_rn(__fadd_rn(xn, g_cnorm[k]), 2.0f * m);
            if (dd < bv || (dd == bv && k < bi)) { bv = dd; bi = k; }
        }
    } else {   // overflow fallback: exact full scan
        for (int k = lane; k < KC; k += 32) {
            const float* cp = cb + (size_t)k * DD;
            float m = 0.f;
#pragma unroll 8
            for (int d = 0; d < DD; ++d) m = fmaf(xs[w][d], cp[d], m);
            float dd = __fsub_rn(__fadd_rn(xn, g_cnorm[k]), 2.0f * m);
            if (dd < bv || (dd == bv && k < bi)) { bv = dd; bi = k; }
        }
    }
#pragma unroll
    for (int off = 16; off; off >>= 1) {
        float ov = __shfl_xor_sync(0xffffffffu, bv, off);
        int   ob = __shfl_xor_sync(0xffffffffu, bi, off);
        if (ov < bv || (ov == bv && ob < bi)) { bv = ov; bi = ob; }
    }
    if (lane == 0) g_idx[n] = bi;
}

// ============================================================
// Kernel 6: gather quant, straight-through output, loss partial.
// ============================================================
__global__ __launch_bounds__(256) void epi_kernel(const float* __restrict__ x,
                                                  const float* __restrict__ cb,
                                                  float* __restrict__ out) {
    __shared__ int   sidx[64];
    __shared__ float swarp[8];
    const int tid  = threadIdx.x;
    const int tok0 = blockIdx.x * 64;
    const int bimg = tok0 >> 10;
    const int hw0  = tok0 & (HW - 1);

    if (tid < 64) sidx[tid] = g_idx[tok0 + tid];
    __syncthreads();

    const int m  = tid & 63;
    const int dh = tid >> 6;
    const size_t base = (size_t)bimg * IMG + hw0 + m;
    const long long crow = (long long)sidx[m] * DD;

    float lsum = 0.f;
#pragma unroll 8
    for (int d0 = 0; d0 < DD; d0 += 4) {
        int d = d0 + dh;
        float q  = cb[crow + d];
        size_t off = base + (size_t)d * HW;
        float xv = x[off];
        float t  = __fsub_rn(q, xv);
        out[off] = __fadd_rn(xv, t);
        lsum = fmaf(t, t, lsum);
    }
#pragma unroll
    for (int off = 16; off; off >>= 1) lsum += __shfl_xor_sync(0xffffffffu, lsum, off);
    if ((tid & 31) == 0) swarp[tid >> 5] = lsum;
    __syncthreads();
    if (tid == 0) {
        float s = 0.f;
        for (int wq = 0; wq < 8; ++wq) s += swarp[wq];
        g_partial[blockIdx.x] = s;
    }
    if (tid < 64) out[OUT_ENC + tok0 + tid] = (float)sidx[tid];
}

// ============================================================
// Kernel 7: finalize loss
// ============================================================
__global__ __launch_bounds__(256) void fin_kernel(float* __restrict__ out) {
    __shared__ float sw[8];
    int tid = threadIdx.x;
    float s = g_partial[tid];
#pragma unroll
    for (int off = 16; off; off >>= 1) s += __shfl_xor_sync(0xffffffffu, s, off);
    if ((tid & 31) == 0) sw[tid >> 5] = s;
    __syncthreads();
    if (tid == 0) {
        float tot = 0.f;
        for (int wq = 0; wq < 8; ++wq) tot += sw[wq];
        float mse = tot / 4194304.0f;
        out[OUT_LOSS] = __fadd_rn(mse, __fmul_rn(0.25f, mse));
    }
}

// ============================================================
extern "C" void kernel_launch(void* const* d_in, const int* in_sizes, int n_in,
                              void* d_out, int out_size) {
    const float* x  = (const float*)d_in[0];   // [16,256,32,32] fp32
    const float* cb = (const float*)d_in[1];   // [8192,256] fp32
    float* out = (float*)d_out;

    norms_kernel<<<96, 256>>>(x, cb);
    convert_kernel<<<3072, 256>>>(x, cb);
    gemm_kernel<<<4096, 512>>>();
    collect_kernel<<<512, 256>>>();
    rescore_kernel<<<NTOK / 8, 256>>>(x, cb);
    epi_kernel<<<256, 256>>>(x, cb, out);
    fin_kernel<<<1, 256>>>(out);
}